// round 6
// baseline (speedup 1.0000x reference)
#include <cuda_runtime.h>

#define F_EPS 1e-10f

// ---------------------------------------------------------------------------
// Uniform (batch-invariant) constants, pre-differenced to minimize live regs
// and per-element FLOPs.
// ---------------------------------------------------------------------------
struct Consts {
    float dmu0, dmu1, b0, b1;   // em_j = p*dmu_j + b_j ; b_j = mu2_j - r
    float dSa, dSb, dSc;        // Sigma1 - Sigma2 entries
    float S2a, S2b, S2c;        // Sigma2 entries (+EPS on diag)
    float phi00, phi01, phi10, phi11;
    float s00, s01, s11;        // spd_core = tril @ tril^T
    float omega, lamh;          // lamh = 0.5 * Lambda
};

// Lambda / r arrive from Python ints -> may be int32 bits or float32 bits.
__device__ __forceinline__ float decode_scalar_bits(int bits) {
    if (bits == 0) return 0.0f;
    float fv = __int_as_float(bits);
    float af = fabsf(fv);
    if (af >= 1e-30f && af <= 1e30f) return fv;   // looks like a float
    return (float)bits;                            // it was an int
}

__device__ __forceinline__ Consts build_consts(const float* __restrict__ omega,
                                               const float* __restrict__ mu1,
                                               const float* __restrict__ mu2,
                                               const float* __restrict__ Sig1,
                                               const float* __restrict__ Sig2,
                                               const float* __restrict__ phi,
                                               const float* __restrict__ ctril,
                                               const int* __restrict__ Lambda,
                                               const int* __restrict__ r) {
    Consts c;
    float4 s1 = __ldg((const float4*)Sig1);   // [a b; b c] row-major
    float4 s2 = __ldg((const float4*)Sig2);
    float4 ph = __ldg((const float4*)phi);    // phi[0,0] phi[0,1] phi[1,0] phi[1,1]
    float4 ctv = __ldg((const float4*)ctril);
    float2 m1 = __ldg((const float2*)mu1);
    float2 m2 = __ldg((const float2*)mu2);

    float rr = decode_scalar_bits(__ldg(r));
    c.dmu0 = m1.x - m2.x;  c.dmu1 = m1.y - m2.y;
    c.b0   = m2.x - rr;    c.b1   = m2.y - rr;
    c.dSa = s1.x - s2.x;   c.dSb = s1.y - s2.y;   c.dSc = s1.w - s2.w;
    c.S2a = s2.x + F_EPS;  c.S2b = s2.y;          c.S2c = s2.w + F_EPS;
    c.phi00 = ph.x; c.phi01 = ph.y;
    c.phi10 = ph.z; c.phi11 = ph.w;
    // tril T = [[exp(C00), 0], [C10, exp(C11)]];  S = T T^T
    float C00 = ctv.x, C10 = ctv.z, C11 = ctv.w;
    float e0 = expf(C00), e1 = expf(C11);
    c.s00 = e0 * e0;
    c.s01 = e0 * C10;
    c.s11 = C10 * C10 + e1 * e1;
    c.omega = __ldg(omega);
    c.lamh = 0.5f * decode_scalar_bits(__ldg(Lambda));
    return c;
}

// ---------------------------------------------------------------------------
// Per-element closed form (N=2). See R0 derivation.
// ---------------------------------------------------------------------------
__device__ __forceinline__ void compute_elem(const Consts& c,
                                             float xv, float pv, float dv, float fv,
                                             float& m0, float& m1, float4& cov) {
    float pm1 = 1.0f - pv;
    float em0 = fmaf(pv, c.dmu0, c.b0);
    float em1 = fmaf(pv, c.dmu1, c.b1);

    float a = fmaf(pv, c.dSa, c.S2a);
    float b = fmaf(pv, c.dSb, c.S2b);
    float d = fmaf(pv, c.dSc, c.S2c);

    float inv_l11 = rsqrtf(a);
    float l21     = b * inv_l11;
    float t       = d - l21 * l21;
    float inv_l22 = rsqrtf(t);

    float adj = pv * fmaf(-dv, pm1, 1.0f);
    float s0 = fmaf(c.phi00, adj, c.phi01) * em0;
    float s1 = fmaf(c.phi10, adj, c.phi11) * em1;

    float sti1 = s1 * inv_l22;
    float sti0 = (s0 - l21 * sti1) * inv_l11;

    float mx = c.omega - xv;
    m0 = mx * sti0;
    m1 = mx * sti1;

    float u00 = inv_l11;
    float u11 = inv_l22;
    float u01 = -l21 * inv_l11 * inv_l22;

    float M00 = u00 * u00 * c.s00 + 2.0f * u00 * u01 * c.s01 + u01 * u01 * c.s11;
    float M01 = u11 * fmaf(u00, c.s01, u01 * c.s11);
    float M11 = u11 * u11 * c.s11;

    float sc = c.lamh * fv;
    cov.x = fmaf(sc, M00, F_EPS);
    cov.y = sc * M01;
    cov.z = sc * M01;
    cov.w = fmaf(sc, M11, F_EPS);
}

// Process a 4-elem batch: compute in pairs, store immediately to cut liveness.
__device__ __forceinline__ void do_batch(const Consts& c, int i0,
                                         float4 xv, float4 pv, float4 dv, float4 fv,
                                         float* __restrict__ out_mean,
                                         float* __restrict__ out_cov) {
    float4* mb = (float4*)(out_mean + (size_t)2 * i0);
    float4* cb = (float4*)(out_cov + (size_t)4 * i0);

    float m0, m1, m2, m3;
    float4 c0, c1;
    compute_elem(c, xv.x, pv.x, dv.x, fv.x, m0, m1, c0);
    compute_elem(c, xv.y, pv.y, dv.y, fv.y, m2, m3, c1);
    mb[0] = make_float4(m0, m1, m2, m3);
    cb[0] = c0; cb[1] = c1;

    compute_elem(c, xv.z, pv.z, dv.z, fv.z, m0, m1, c0);
    compute_elem(c, xv.w, pv.w, dv.w, fv.w, m2, m3, c1);
    mb[1] = make_float4(m0, m1, m2, m3);
    cb[2] = c0; cb[3] = c1;
}

#define THREADS 256
#define CHUNK   (THREADS * 4)       // 1024 elems per iteration
#define BLK_EL  (CHUNK * 2)         // 2048 elems per block (2 pipelined batches)

__global__ void __launch_bounds__(THREADS)
poemv_kernel(const float* __restrict__ x, const float* __restrict__ p,
             const float* __restrict__ dlnf, const float* __restrict__ f,
             float* __restrict__ out_mean, float* __restrict__ out_cov, int B,
             const float* __restrict__ omega, const float* __restrict__ mu1,
             const float* __restrict__ mu2, const float* __restrict__ S1,
             const float* __restrict__ S2, const float* __restrict__ phi,
             const float* __restrict__ ct, const int* __restrict__ Lam,
             const int* __restrict__ rr) {
    const Consts c = build_consts(omega, mu1, mu2, S1, S2, phi, ct, Lam, rr);

    int base = blockIdx.x * BLK_EL;
    int i0 = base + threadIdx.x * 4;          // batch 0
    int i1 = i0 + CHUNK;                       // batch 1

    if (i1 + 3 < B) {
        // --- stage 0 loads (MLP_p1 = 4) ---
        float4 xa = *(const float4*)(x + i0);
        float4 pa = *(const float4*)(p + i0);
        float4 da = *(const float4*)(dlnf + i0);
        float4 fa = *(const float4*)(f + i0);

        // compute first pair of batch 0 (forces the wait on loads0)
        float m0, m1, m2, m3;
        float4 c0, c1;
        compute_elem(c, xa.x, pa.x, da.x, fa.x, m0, m1, c0);
        compute_elem(c, xa.y, pa.y, da.y, fa.y, m2, m3, c1);

        // --- stage 1 loads: issued while batch-0 stores/compute proceed ---
        float4 xb = *(const float4*)(x + i1);
        float4 pb = *(const float4*)(p + i1);
        float4 db = *(const float4*)(dlnf + i1);
        float4 fb = *(const float4*)(f + i1);

        // finish batch 0 (stores overlap stage-1 loads in flight)
        float4* mb = (float4*)(out_mean + (size_t)2 * i0);
        float4* cb = (float4*)(out_cov + (size_t)4 * i0);
        mb[0] = make_float4(m0, m1, m2, m3);
        cb[0] = c0; cb[1] = c1;
        compute_elem(c, xa.z, pa.z, da.z, fa.z, m0, m1, c0);
        compute_elem(c, xa.w, pa.w, da.w, fa.w, m2, m3, c1);
        mb[1] = make_float4(m0, m1, m2, m3);
        cb[2] = c0; cb[3] = c1;

        // batch 1: loads have had ~a full batch of compute+stores to land
        do_batch(c, i1, xb, pb, db, fb, out_mean, out_cov);
    } else {
        // tail: scalar with bounds checks over both batches
        for (int s = 0; s < 2; s++) {
            int ib = (s == 0) ? i0 : i1;
            for (int k = 0; k < 4; k++) {
                int i = ib + k;
                if (i < B) {
                    float q0, q1; float4 cvv;
                    compute_elem(c, x[i], p[i], dlnf[i], f[i], q0, q1, cvv);
                    out_mean[(size_t)2 * i]     = q0;
                    out_mean[(size_t)2 * i + 1] = q1;
                    float* cb = out_cov + (size_t)4 * i;
                    cb[0] = cvv.x; cb[1] = cvv.y; cb[2] = cvv.z; cb[3] = cvv.w;
                }
            }
        }
    }
}

extern "C" void kernel_launch(void* const* d_in, const int* in_sizes, int n_in,
                              void* d_out, int out_size) {
    const float* x     = (const float*)d_in[0];
    const float* omega = (const float*)d_in[1];
    const float* p     = (const float*)d_in[2];
    const float* dlnf  = (const float*)d_in[3];
    const float* f     = (const float*)d_in[4];
    const float* mu1   = (const float*)d_in[5];
    const float* mu2   = (const float*)d_in[6];
    const float* S1    = (const float*)d_in[7];
    const float* S2    = (const float*)d_in[8];
    const float* phi   = (const float*)d_in[9];
    const float* ct    = (const float*)d_in[10];
    const int*   Lam   = (const int*)d_in[11];
    const int*   r     = (const int*)d_in[12];

    int B = in_sizes[0];
    float* out      = (float*)d_out;
    float* out_mean = out;                       // (B, 2) flattened
    float* out_cov  = out + (size_t)B * 2;       // (B, 2, 2) flattened

    int grid = (B + BLK_EL - 1) / BLK_EL;
    poemv_kernel<<<grid, THREADS>>>(x, p, dlnf, f, out_mean, out_cov, B,
                                    omega, mu1, mu2, S1, S2, phi, ct, Lam, r);
}